// round 4
// baseline (speedup 1.0000x reference)
#include <cuda_runtime.h>

// Problem shape (fixed per dataset)
#define MAXN 50000
#define MAXE 800000
#define HH   128
#define GG   64
#define OO   64

// ---------------- scratch (static device globals; no allocs) ----------------
__device__ __align__(128) float    g_h   [MAXN * HH];
__device__ __align__(128) float    g_hp  [MAXN * HH];
__device__ __align__(128) float    g_asp [4 * MAXN];   // as(b0), as(b1), ad(b0), ad(b1)
__device__ __align__(128) float    g_pool[GG * HH];
// CSR scratch
__device__ __align__(128) int g_counts[MAXN];
__device__ __align__(128) int g_part  [MAXN];
__device__ __align__(128) int g_rowptr[MAXN + 1];
__device__ __align__(128) int g_fillp [MAXN];
__device__ __align__(128) int g_bsum  [256];
__device__ __align__(128) int g_col   [MAXE + MAXN];
__device__ int g_is64;

// ---------------- helpers ----------------
__device__ __forceinline__ int ld_idx(const void* p, long i, int is64) {
    if (is64) return (int)((const long long*)p)[i];
    return ((const int*)p)[i];
}

// packed f32x2 (Blackwell)
__device__ __forceinline__ unsigned long long dup2(float x) {
    unsigned long long r;
    unsigned xi = __float_as_uint(x);
    asm("mov.b64 %0, {%1, %1};" : "=l"(r) : "r"(xi));
    return r;
}
__device__ __forceinline__ unsigned long long ffma2(unsigned long long a,
                                                    unsigned long long b,
                                                    unsigned long long c) {
    asm("fma.rn.f32x2 %0, %1, %2, %3;" : "=l"(c) : "l"(a), "l"(b), "l"(c));
    return c;
}
__device__ __forceinline__ float2 unpk(unsigned long long v) {
    unsigned lo, hi;
    asm("mov.b64 {%0, %1}, %2;" : "=r"(lo), "=r"(hi) : "l"(v));
    float2 r; r.x = __uint_as_float(lo); r.y = __uint_as_float(hi);
    return r;
}

// ---------------- kernels ----------------

__global__ void k_detect(const unsigned long long* ei) {
    if (threadIdx.x == 0 && blockIdx.x == 0) {
        int is64 = 1;
        for (int i = 0; i < 64; i++)
            if (ei[i] > 1000000ull) is64 = 0;
        g_is64 = is64;
    }
}

__global__ void k_zero_i(int* p, int n) {
    int i = blockIdx.x * blockDim.x + threadIdx.x;
    if (i < n) p[i] = 0;
}
__global__ void k_zero(float4* p, int n4) {
    int i = blockIdx.x * blockDim.x + threadIdx.x;
    if (i < n4) p[i] = make_float4(0.f, 0.f, 0.f, 0.f);
}

// ---- CSR build (once per launch) ----
__global__ void k_hist(const void* ei, int* counts, int E, int n) {
    int e = blockIdx.x * blockDim.x + threadIdx.x;
    if (e >= E + n) return;
    int d = (e < E) ? ld_idx(ei, (long)E + e, g_is64) : (e - E);
    atomicAdd(&counts[d], 1);
}

__global__ __launch_bounds__(1024) void k_scanA(const int* counts, int* part,
                                                int* bsum, int n) {
    __shared__ int ws[32];
    int i = blockIdx.x * 1024 + threadIdx.x;
    int lane = threadIdx.x & 31, wid = threadIdx.x >> 5;
    int x = (i < n) ? counts[i] : 0;
#pragma unroll
    for (int o = 1; o < 32; o <<= 1) {
        int y = __shfl_up_sync(0xffffffffu, x, o);
        if (lane >= o) x += y;
    }
    if (lane == 31) ws[wid] = x;
    __syncthreads();
    if (wid == 0) {
        int y = ws[lane];
#pragma unroll
        for (int o = 1; o < 32; o <<= 1) {
            int z = __shfl_up_sync(0xffffffffu, y, o);
            if (lane >= o) y += z;
        }
        ws[lane] = y;
    }
    __syncthreads();
    int incl = x + (wid ? ws[wid - 1] : 0);
    if (i < n) part[i] = incl;
    if (threadIdx.x == 1023) bsum[blockIdx.x] = incl;   // raw block totals
}

// rowptr + fillp in one pass; per-block prefix of bsum computed serially
// (each 256-thread block covers i with a single i>>10 value).
__global__ void k_scanC(const int* part, const int* bsum, const int* counts,
                        int* rowptr, int* fillp, int n) {
    __shared__ int pref;
    if (threadIdx.x == 0) {
        int target = blockIdx.x >> 2;   // (b*256)>>10
        int run = 0;
        for (int k = 0; k < target; k++) run += bsum[k];
        pref = run;
    }
    __syncthreads();
    int i = blockIdx.x * 256 + threadIdx.x;
    if (i == 0) rowptr[0] = 0;
    if (i < n) {
        int incl = part[i] + pref;
        rowptr[i + 1] = incl;
        fillp[i] = incl - counts[i];
    }
}
__global__ void k_fill(const void* ei, int* fillp, int* col, int E, int n) {
    int e = blockIdx.x * blockDim.x + threadIdx.x;
    if (e >= E + n) return;
    int is64 = g_is64;
    int s, d;
    if (e < E) { s = ld_idx(ei, e, is64); d = ld_idx(ei, (long)E + e, is64); }
    else       { s = d = e - E; }
    int pos = atomicAdd(&fillp[d], 1);
    col[pos] = s;
}

// C[nrows,128] = A[nrows,128] @ W[128,128] (+bias). 64x64 tile, 128 threads,
// packed f32x2 FMA. If a_s != nullptr, also writes race-free per-col-block
// alpha partials: asp[row + by*n] (src) and asp[row + 2n + by*n] (dst).
__global__ __launch_bounds__(128) void k_gemm(const float* __restrict__ A,
                                              const float* __restrict__ W,
                                              const float* __restrict__ bias,
                                              const float* __restrict__ a_s,
                                              const float* __restrict__ a_d,
                                              float* __restrict__ asp,
                                              float* __restrict__ C, int nrows) {
    extern __shared__ float smem[];
    float (*As)[132] = (float(*)[132])smem;        // 64 x 132 (padded)
    float* Ws = smem + 64 * 132;                   // 128 x 64

    int t = threadIdx.x;
    int row0 = blockIdx.x * 64;
    int col0 = blockIdx.y * 64;

    for (int i = t; i < 128 * 16; i += 128) {
        int k = i >> 4, n4 = (i & 15) << 2;
        *(float4*)&Ws[k * 64 + n4] = *(const float4*)&W[k * HH + col0 + n4];
    }
    for (int i = t; i < 64 * 32; i += 128) {
        int mm = i >> 5, k4 = (i & 31) << 2;
        float4 v = make_float4(0.f, 0.f, 0.f, 0.f);
        if (row0 + mm < nrows) v = *(const float4*)&A[(long)(row0 + mm) * HH + k4];
        *(float4*)&As[mm][k4] = v;
    }
    __syncthreads();

    int tx = t & 7, ty = t >> 3;
    int rb = ty << 2, cb = tx << 3;
    unsigned long long acc[4][4];
#pragma unroll
    for (int r = 0; r < 4; r++)
#pragma unroll
        for (int c = 0; c < 4; c++) acc[r][c] = 0ull;

#pragma unroll 8
    for (int k = 0; k < 128; k++) {
        const unsigned long long* wp = (const unsigned long long*)&Ws[k * 64 + cb];
        unsigned long long w0 = wp[0], w1 = wp[1], w2 = wp[2], w3 = wp[3];
#pragma unroll
        for (int r = 0; r < 4; r++) {
            unsigned long long a2 = dup2(As[rb + r][k]);
            acc[r][0] = ffma2(a2, w0, acc[r][0]);
            acc[r][1] = ffma2(a2, w1, acc[r][1]);
            acc[r][2] = ffma2(a2, w2, acc[r][2]);
            acc[r][3] = ffma2(a2, w3, acc[r][3]);
        }
    }

    float av_s[8], av_d[8];
    if (a_s) {
        float4 s0 = *(const float4*)&a_s[col0 + cb];
        float4 s1 = *(const float4*)&a_s[col0 + cb + 4];
        float4 d0 = *(const float4*)&a_d[col0 + cb];
        float4 d1 = *(const float4*)&a_d[col0 + cb + 4];
        av_s[0] = s0.x; av_s[1] = s0.y; av_s[2] = s0.z; av_s[3] = s0.w;
        av_s[4] = s1.x; av_s[5] = s1.y; av_s[6] = s1.z; av_s[7] = s1.w;
        av_d[0] = d0.x; av_d[1] = d0.y; av_d[2] = d0.z; av_d[3] = d0.w;
        av_d[4] = d1.x; av_d[5] = d1.y; av_d[6] = d1.z; av_d[7] = d1.w;
    }

#pragma unroll
    for (int r = 0; r < 4; r++) {
        int row = row0 + rb + r;
        if (row >= nrows) continue;
        float o[8];
#pragma unroll
        for (int c = 0; c < 4; c++) {
            float2 p = unpk(acc[r][c]);
            o[2 * c] = p.x; o[2 * c + 1] = p.y;
        }
        if (bias) {
            float4 b0 = *(const float4*)&bias[col0 + cb];
            float4 b1 = *(const float4*)&bias[col0 + cb + 4];
            o[0] += b0.x; o[1] += b0.y; o[2] += b0.z; o[3] += b0.w;
            o[4] += b1.x; o[5] += b1.y; o[6] += b1.z; o[7] += b1.w;
        }
        if (a_s) {
            float ps = 0.f, pd = 0.f;
#pragma unroll
            for (int c = 0; c < 8; c++) {
                ps = fmaf(o[c], av_s[c], ps);
                pd = fmaf(o[c], av_d[c], pd);
            }
#pragma unroll
            for (int off = 4; off > 0; off >>= 1) {
                ps += __shfl_xor_sync(0xffffffffu, ps, off);
                pd += __shfl_xor_sync(0xffffffffu, pd, off);
            }
            if (tx == 0) {   // unique writer per (row, col-block): no atomics
                asp[row + blockIdx.y * nrows]              = ps;
                asp[row + 2 * nrows + blockIdx.y * nrows]  = pd;
            }
        }
        *(float4*)&C[(long)row * HH + col0 + cb]     = make_float4(o[0], o[1], o[2], o[3]);
        *(float4*)&C[(long)row * HH + col0 + cb + 4] = make_float4(o[4], o[5], o[6], o[7]);
    }
}

// warp per destination node: softmax over in-edges + weighted gather of hp[src].
// alpha scores assembled from the two GEMM col-block partials on the fly.
__global__ __launch_bounds__(256) void k_aggregate(
    const int* __restrict__ rowptr, const int* __restrict__ col,
    const float* __restrict__ asp,
    const float* __restrict__ hp, const float* __restrict__ bias,
    float* __restrict__ hout, int n, int relu) {
    int gid = blockIdx.x * blockDim.x + threadIdx.x;
    int w = gid >> 5, lane = gid & 31;
    if (w >= n) return;
    int beg = rowptr[w], end = rowptr[w + 1];
    const float* as0 = asp;
    const float* as1 = asp + n;
    float add = __ldg(&asp[w + 2 * n]) + __ldg(&asp[w + 3 * n]);

    // online softmax stats over in-edges
    float m = -3.4e38f, den = 0.f;
    for (int j = beg + lane; j < end; j += 32) {
        int s = __ldg(&col[j]);
        float v = __ldg(&as0[s]) + __ldg(&as1[s]) + add;
        v = v >= 0.f ? v : 0.2f * v;
        if (v > m) { den = den * __expf(m - v) + 1.f; m = v; }
        else den += __expf(v - m);
    }
#pragma unroll
    for (int o = 16; o > 0; o >>= 1) {
        float mo = __shfl_xor_sync(0xffffffffu, m, o);
        float dd = __shfl_xor_sync(0xffffffffu, den, o);
        float M = fmaxf(m, mo);
        den = den * __expf(m - M) + dd * __expf(mo - M);
        m = M;
    }
    float inv = 1.f / den;

    // weighted gather: per-edge uniform (broadcast) loads, unrolled for MLP
    float4 acc = make_float4(0.f, 0.f, 0.f, 0.f);
    int j = beg;
#pragma unroll 1
    for (; j + 4 <= end; j += 4) {
        int   s0 = __ldg(&col[j]),     s1 = __ldg(&col[j + 1]);
        int   s2 = __ldg(&col[j + 2]), s3 = __ldg(&col[j + 3]);
        float v0 = __ldg(&as0[s0]) + __ldg(&as1[s0]) + add;
        float v1 = __ldg(&as0[s1]) + __ldg(&as1[s1]) + add;
        float v2 = __ldg(&as0[s2]) + __ldg(&as1[s2]) + add;
        float v3 = __ldg(&as0[s3]) + __ldg(&as1[s3]) + add;
        v0 = v0 >= 0.f ? v0 : 0.2f * v0;  v1 = v1 >= 0.f ? v1 : 0.2f * v1;
        v2 = v2 >= 0.f ? v2 : 0.2f * v2;  v3 = v3 >= 0.f ? v3 : 0.2f * v3;
        float a0 = __expf(v0 - m) * inv, a1 = __expf(v1 - m) * inv;
        float a2 = __expf(v2 - m) * inv, a3 = __expf(v3 - m) * inv;
        float4 h0 = __ldg(&((const float4*)hp)[(long)s0 * 32 + lane]);
        float4 h1 = __ldg(&((const float4*)hp)[(long)s1 * 32 + lane]);
        float4 h2 = __ldg(&((const float4*)hp)[(long)s2 * 32 + lane]);
        float4 h3 = __ldg(&((const float4*)hp)[(long)s3 * 32 + lane]);
        acc.x = fmaf(a0, h0.x, acc.x); acc.y = fmaf(a0, h0.y, acc.y);
        acc.z = fmaf(a0, h0.z, acc.z); acc.w = fmaf(a0, h0.w, acc.w);
        acc.x = fmaf(a1, h1.x, acc.x); acc.y = fmaf(a1, h1.y, acc.y);
        acc.z = fmaf(a1, h1.z, acc.z); acc.w = fmaf(a1, h1.w, acc.w);
        acc.x = fmaf(a2, h2.x, acc.x); acc.y = fmaf(a2, h2.y, acc.y);
        acc.z = fmaf(a2, h2.z, acc.z); acc.w = fmaf(a2, h2.w, acc.w);
        acc.x = fmaf(a3, h3.x, acc.x); acc.y = fmaf(a3, h3.y, acc.y);
        acc.z = fmaf(a3, h3.z, acc.z); acc.w = fmaf(a3, h3.w, acc.w);
    }
    for (; j < end; j++) {
        int   s0 = __ldg(&col[j]);
        float v0 = __ldg(&as0[s0]) + __ldg(&as1[s0]) + add;
        v0 = v0 >= 0.f ? v0 : 0.2f * v0;
        float a0 = __expf(v0 - m) * inv;
        float4 h0 = __ldg(&((const float4*)hp)[(long)s0 * 32 + lane]);
        acc.x = fmaf(a0, h0.x, acc.x); acc.y = fmaf(a0, h0.y, acc.y);
        acc.z = fmaf(a0, h0.z, acc.z); acc.w = fmaf(a0, h0.w, acc.w);
    }
    float4 bb = ((const float4*)bias)[lane];
    acc.x += bb.x; acc.y += bb.y; acc.z += bb.z; acc.w += bb.w;
    if (relu) {
        acc.x = fmaxf(acc.x, 0.f); acc.y = fmaxf(acc.y, 0.f);
        acc.z = fmaxf(acc.z, 0.f); acc.w = fmaxf(acc.w, 0.f);
    }
    ((float4*)hout)[(long)w * 32 + lane] = acc;
}

// global_add_pool over sorted batch
__global__ void k_pool(const float* __restrict__ h, const void* batch,
                       float* __restrict__ pool, int n) {
    __shared__ float s[GG * HH];
    for (int i = threadIdx.x; i < GG * HH; i += 256) s[i] = 0.f;
    __syncthreads();
    int is64 = g_is64;
    int per = (n + gridDim.x - 1) / gridDim.x;
    int i0 = blockIdx.x * per;
    int i1 = min(n, i0 + per);
    int c = threadIdx.x & 127, sub = threadIdx.x >> 7;
    float accv = 0.f; int curg = -1;
    for (int r = i0 + sub; r < i1; r += 2) {
        int g = ld_idx(batch, r, is64);
        if (g != curg) {
            if (curg >= 0) atomicAdd(&s[curg * HH + c], accv);
            accv = 0.f; curg = g;
        }
        accv += h[(long)r * HH + c];
    }
    if (curg >= 0) atomicAdd(&s[curg * HH + c], accv);
    __syncthreads();
    for (int i = threadIdx.x; i < GG * HH; i += 256) {
        float v = s[i];
        if (v != 0.f) atomicAdd(&pool[i], v);
    }
}

__global__ void k_final(const float* __restrict__ pool, const float* __restrict__ Wf,
                        const float* __restrict__ bf, float* __restrict__ out) {
    int i = blockIdx.x * blockDim.x + threadIdx.x;
    if (i >= GG * OO) return;
    int g = i >> 6, o = i & 63;
    float sa = bf[o];
#pragma unroll 8
    for (int k = 0; k < HH; k++) sa += pool[g * HH + k] * Wf[k * OO + o];
    out[i] = sa;
}

// ---------------- launch ----------------
extern "C" void kernel_launch(void* const* d_in, const int* in_sizes, int n_in,
                              void* d_out, int out_size) {
    const float* x     = (const float*)d_in[0];
    const void*  ei    = d_in[1];
    const void*  batch = d_in[2];
    const float* W0    = (const float*)d_in[3];
    const float* b0    = (const float*)d_in[4];
    const float* Wl    = (const float*)d_in[5];
    const float* a_src = (const float*)d_in[6];
    const float* a_dst = (const float*)d_in[7];
    const float* bl    = (const float*)d_in[8];
    const float* Wf    = (const float*)d_in[9];
    const float* bf    = (const float*)d_in[10];
    float* out = (float*)d_out;

    int n  = in_sizes[0] / HH;
    int E  = in_sizes[1] / 2;
    int et = E + n;
    int L  = in_sizes[5] / (HH * HH);

    float *h, *hp, *asp, *pool;
    int *counts, *part, *rowptr, *fillp, *bsum, *col;
    cudaGetSymbolAddress((void**)&h,    g_h);
    cudaGetSymbolAddress((void**)&hp,   g_hp);
    cudaGetSymbolAddress((void**)&asp,  g_asp);
    cudaGetSymbolAddress((void**)&pool, g_pool);
    cudaGetSymbolAddress((void**)&counts, g_counts);
    cudaGetSymbolAddress((void**)&part,   g_part);
    cudaGetSymbolAddress((void**)&rowptr, g_rowptr);
    cudaGetSymbolAddress((void**)&fillp,  g_fillp);
    cudaGetSymbolAddress((void**)&bsum,   g_bsum);
    cudaGetSymbolAddress((void**)&col,    g_col);

    const int gemm_smem = (64 * 132 + 128 * 64) * sizeof(float);
    cudaFuncSetAttribute(k_gemm, cudaFuncAttributeMaxDynamicSharedMemorySize, gemm_smem);

    dim3 ggrid((n + 63) / 64, HH / 64);
    int nb = (n + 1023) / 1024;

    // side stream + fork/join events (created once, on the uncaptured
    // correctness call; reused identically in every capture/replay)
    static cudaStream_t s2 = nullptr;
    static cudaEvent_t evF = nullptr, evJ = nullptr;
    if (s2 == nullptr) {
        cudaStreamCreateWithFlags(&s2, cudaStreamNonBlocking);
        cudaEventCreateWithFlags(&evF, cudaEventDisableTiming);
        cudaEventCreateWithFlags(&evJ, cudaEventDisableTiming);
    }

    // main: detect (g_is64 needed by CSR branch)
    k_detect<<<1, 32>>>((const unsigned long long*)ei);

    // fork: CSR build + pool zeroing on s2, GEMM0 on main stream
    cudaEventRecord(evF, 0);
    cudaStreamWaitEvent(s2, evF, 0);
    k_zero_i<<<(n + 255) / 256, 256, 0, s2>>>(counts, n);
    k_hist<<<(et + 255) / 256, 256, 0, s2>>>(ei, counts, E, n);
    k_scanA<<<nb, 1024, 0, s2>>>(counts, part, bsum, n);
    k_scanC<<<(n + 255) / 256, 256, 0, s2>>>(part, bsum, counts, rowptr, fillp, n);
    k_fill<<<(et + 255) / 256, 256, 0, s2>>>(ei, fillp, col, E, n);
    k_zero<<<(GG * HH / 4 + 255) / 256, 256, 0, s2>>>((float4*)pool, GG * HH / 4);
    cudaEventRecord(evJ, s2);

    // main: h = x @ W0 + b0  (overlaps CSR build)
    k_gemm<<<ggrid, 128, gemm_smem>>>(x, W0, b0, nullptr, nullptr, nullptr, h, n);

    // join
    cudaStreamWaitEvent(0, evJ, 0);

    for (int l = 0; l < L; l++) {
        k_gemm<<<ggrid, 128, gemm_smem>>>(h, Wl + (long)l * HH * HH, nullptr,
                                          a_src + l * HH, a_dst + l * HH,
                                          asp, hp, n);
        k_aggregate<<<(n * 32 + 255) / 256, 256>>>(rowptr, col, asp, hp,
                                                   bl + l * HH, h, n,
                                                   (l < L - 1) ? 1 : 0);
    }

    k_pool<<<64, 256>>>(h, batch, pool, n);
    k_final<<<(GG * OO + 255) / 256, 256>>>(pool, Wf, bf, out);
}

// round 5
// speedup vs baseline: 1.0220x; 1.0220x over previous
#include <cuda_runtime.h>

// Problem shape (fixed per dataset)
#define MAXN 50000
#define MAXE 800000
#define HH   128
#define GG   64
#define OO   64

// ---------------- scratch (static device globals; no allocs) ----------------
__device__ __align__(128) float    g_h   [MAXN * HH];
__device__ __align__(128) float    g_hp  [MAXN * HH];
__device__ __align__(128) float    g_asp [4 * MAXN];   // as(b0), as(b1), ad(b0), ad(b1)
__device__ __align__(128) float    g_asum[2 * MAXN];   // combined as, ad
__device__ __align__(128) float    g_ev  [MAXE + MAXN];// per-edge leaky score
__device__ __align__(128) float    g_pool[GG * HH];
// CSR scratch
__device__ __align__(128) int g_counts[MAXN];
__device__ __align__(128) int g_part  [MAXN];
__device__ __align__(128) int g_rowptr[MAXN + 1];
__device__ __align__(128) int g_fillp [MAXN];
__device__ __align__(128) int g_bsum  [256];
__device__ __align__(128) int g_col   [MAXE + MAXN];
__device__ int g_is64;

// ---------------- helpers ----------------
__device__ __forceinline__ int ld_idx(const void* p, long i, int is64) {
    if (is64) return (int)((const long long*)p)[i];
    return ((const int*)p)[i];
}

// packed f32x2 (Blackwell)
__device__ __forceinline__ unsigned long long dup2(float x) {
    unsigned long long r;
    unsigned xi = __float_as_uint(x);
    asm("mov.b64 %0, {%1, %1};" : "=l"(r) : "r"(xi));
    return r;
}
__device__ __forceinline__ unsigned long long ffma2(unsigned long long a,
                                                    unsigned long long b,
                                                    unsigned long long c) {
    asm("fma.rn.f32x2 %0, %1, %2, %3;" : "=l"(c) : "l"(a), "l"(b), "l"(c));
    return c;
}
__device__ __forceinline__ float2 unpk(unsigned long long v) {
    unsigned lo, hi;
    asm("mov.b64 {%0, %1}, %2;" : "=r"(lo), "=r"(hi) : "l"(v));
    float2 r; r.x = __uint_as_float(lo); r.y = __uint_as_float(hi);
    return r;
}

// ---------------- kernels ----------------

__global__ void k_detect(const unsigned long long* ei) {
    if (threadIdx.x == 0 && blockIdx.x == 0) {
        int is64 = 1;
        for (int i = 0; i < 64; i++)
            if (ei[i] > 1000000ull) is64 = 0;
        g_is64 = is64;
    }
}

__global__ void k_zero_i(int* p, int n) {
    int i = blockIdx.x * blockDim.x + threadIdx.x;
    if (i < n) p[i] = 0;
}
__global__ void k_zero(float4* p, int n4) {
    int i = blockIdx.x * blockDim.x + threadIdx.x;
    if (i < n4) p[i] = make_float4(0.f, 0.f, 0.f, 0.f);
}

// ---- CSR build (once per launch) ----
__global__ void k_hist(const void* ei, int* counts, int E, int n) {
    int e = blockIdx.x * blockDim.x + threadIdx.x;
    if (e >= E + n) return;
    int d = (e < E) ? ld_idx(ei, (long)E + e, g_is64) : (e - E);
    atomicAdd(&counts[d], 1);
}

__global__ __launch_bounds__(1024) void k_scanA(const int* counts, int* part,
                                                int* bsum, int n) {
    __shared__ int ws[32];
    int i = blockIdx.x * 1024 + threadIdx.x;
    int lane = threadIdx.x & 31, wid = threadIdx.x >> 5;
    int x = (i < n) ? counts[i] : 0;
#pragma unroll
    for (int o = 1; o < 32; o <<= 1) {
        int y = __shfl_up_sync(0xffffffffu, x, o);
        if (lane >= o) x += y;
    }
    if (lane == 31) ws[wid] = x;
    __syncthreads();
    if (wid == 0) {
        int y = ws[lane];
#pragma unroll
        for (int o = 1; o < 32; o <<= 1) {
            int z = __shfl_up_sync(0xffffffffu, y, o);
            if (lane >= o) y += z;
        }
        ws[lane] = y;
    }
    __syncthreads();
    int incl = x + (wid ? ws[wid - 1] : 0);
    if (i < n) part[i] = incl;
    if (threadIdx.x == 1023) bsum[blockIdx.x] = incl;   // raw block totals
}

// rowptr + fillp in one pass; per-block prefix of bsum computed serially
__global__ void k_scanC(const int* part, const int* bsum, const int* counts,
                        int* rowptr, int* fillp, int n) {
    __shared__ int pref;
    if (threadIdx.x == 0) {
        int target = blockIdx.x >> 2;   // (b*256)>>10
        int run = 0;
        for (int k = 0; k < target; k++) run += bsum[k];
        pref = run;
    }
    __syncthreads();
    int i = blockIdx.x * 256 + threadIdx.x;
    if (i == 0) rowptr[0] = 0;
    if (i < n) {
        int incl = part[i] + pref;
        rowptr[i + 1] = incl;
        fillp[i] = incl - counts[i];
    }
}
__global__ void k_fill(const void* ei, int* fillp, int* col, int E, int n) {
    int e = blockIdx.x * blockDim.x + threadIdx.x;
    if (e >= E + n) return;
    int is64 = g_is64;
    int s, d;
    if (e < E) { s = ld_idx(ei, e, is64); d = ld_idx(ei, (long)E + e, is64); }
    else       { s = d = e - E; }
    int pos = atomicAdd(&fillp[d], 1);
    col[pos] = s;
}

// C[nrows,128] = A[nrows,128] @ W[128,128] (+bias). 64x64 tile, 128 threads,
// packed f32x2 FMA. If a_s != nullptr, writes race-free per-col-block alpha
// partials asp[row + by*n] (src) / asp[row + 2n + by*n] (dst).
__global__ __launch_bounds__(128) void k_gemm(const float* __restrict__ A,
                                              const float* __restrict__ W,
                                              const float* __restrict__ bias,
                                              const float* __restrict__ a_s,
                                              const float* __restrict__ a_d,
                                              float* __restrict__ asp,
                                              float* __restrict__ C, int nrows) {
    extern __shared__ float smem[];
    float (*As)[132] = (float(*)[132])smem;        // 64 x 132 (padded)
    float* Ws = smem + 64 * 132;                   // 128 x 64

    int t = threadIdx.x;
    int row0 = blockIdx.x * 64;
    int col0 = blockIdx.y * 64;

    for (int i = t; i < 128 * 16; i += 128) {
        int k = i >> 4, n4 = (i & 15) << 2;
        *(float4*)&Ws[k * 64 + n4] = *(const float4*)&W[k * HH + col0 + n4];
    }
    for (int i = t; i < 64 * 32; i += 128) {
        int mm = i >> 5, k4 = (i & 31) << 2;
        float4 v = make_float4(0.f, 0.f, 0.f, 0.f);
        if (row0 + mm < nrows) v = *(const float4*)&A[(long)(row0 + mm) * HH + k4];
        *(float4*)&As[mm][k4] = v;
    }
    __syncthreads();

    int tx = t & 7, ty = t >> 3;
    int rb = ty << 2, cb = tx << 3;
    unsigned long long acc[4][4];
#pragma unroll
    for (int r = 0; r < 4; r++)
#pragma unroll
        for (int c = 0; c < 4; c++) acc[r][c] = 0ull;

#pragma unroll 8
    for (int k = 0; k < 128; k++) {
        const unsigned long long* wp = (const unsigned long long*)&Ws[k * 64 + cb];
        unsigned long long w0 = wp[0], w1 = wp[1], w2 = wp[2], w3 = wp[3];
#pragma unroll
        for (int r = 0; r < 4; r++) {
            unsigned long long a2 = dup2(As[rb + r][k]);
            acc[r][0] = ffma2(a2, w0, acc[r][0]);
            acc[r][1] = ffma2(a2, w1, acc[r][1]);
            acc[r][2] = ffma2(a2, w2, acc[r][2]);
            acc[r][3] = ffma2(a2, w3, acc[r][3]);
        }
    }

    float av_s[8], av_d[8];
    if (a_s) {
        float4 s0 = *(const float4*)&a_s[col0 + cb];
        float4 s1 = *(const float4*)&a_s[col0 + cb + 4];
        float4 d0 = *(const float4*)&a_d[col0 + cb];
        float4 d1 = *(const float4*)&a_d[col0 + cb + 4];
        av_s[0] = s0.x; av_s[1] = s0.y; av_s[2] = s0.z; av_s[3] = s0.w;
        av_s[4] = s1.x; av_s[5] = s1.y; av_s[6] = s1.z; av_s[7] = s1.w;
        av_d[0] = d0.x; av_d[1] = d0.y; av_d[2] = d0.z; av_d[3] = d0.w;
        av_d[4] = d1.x; av_d[5] = d1.y; av_d[6] = d1.z; av_d[7] = d1.w;
    }

#pragma unroll
    for (int r = 0; r < 4; r++) {
        int row = row0 + rb + r;
        if (row >= nrows) continue;
        float o[8];
#pragma unroll
        for (int c = 0; c < 4; c++) {
            float2 p = unpk(acc[r][c]);
            o[2 * c] = p.x; o[2 * c + 1] = p.y;
        }
        if (bias) {
            float4 b0 = *(const float4*)&bias[col0 + cb];
            float4 b1 = *(const float4*)&bias[col0 + cb + 4];
            o[0] += b0.x; o[1] += b0.y; o[2] += b0.z; o[3] += b0.w;
            o[4] += b1.x; o[5] += b1.y; o[6] += b1.z; o[7] += b1.w;
        }
        if (a_s) {
            float ps = 0.f, pd = 0.f;
#pragma unroll
            for (int c = 0; c < 8; c++) {
                ps = fmaf(o[c], av_s[c], ps);
                pd = fmaf(o[c], av_d[c], pd);
            }
#pragma unroll
            for (int off = 4; off > 0; off >>= 1) {
                ps += __shfl_xor_sync(0xffffffffu, ps, off);
                pd += __shfl_xor_sync(0xffffffffu, pd, off);
            }
            if (tx == 0) {   // unique writer per (row, col-block): no atomics
                asp[row + blockIdx.y * nrows]              = ps;
                asp[row + 2 * nrows + blockIdx.y * nrows]  = pd;
            }
        }
        *(float4*)&C[(long)row * HH + col0 + cb]     = make_float4(o[0], o[1], o[2], o[3]);
        *(float4*)&C[(long)row * HH + col0 + cb + 4] = make_float4(o[4], o[5], o[6], o[7]);
    }
}

// combine the two col-block partials: asum[i] = as, asum[i+n] = ad
__global__ void k_combine(const float* __restrict__ asp, float* __restrict__ asum,
                          int n) {
    int i = blockIdx.x * blockDim.x + threadIdx.x;
    if (i >= n) return;
    asum[i]     = asp[i] + asp[i + n];
    asum[i + n] = asp[i + 2 * n] + asp[i + 3 * n];
}

// warp per destination node. Pass 1: gather as[src], compute leaky score,
// STORE it to ev[] (contiguous), online max/denom. Pass 2: read ev[] back
// (sequential) + gather hp[src] — no random score re-gather.
__global__ __launch_bounds__(256) void k_aggregate(
    const int* __restrict__ rowptr, const int* __restrict__ col,
    const float* __restrict__ asum, float* __restrict__ ev,
    const float* __restrict__ hp, const float* __restrict__ bias,
    float* __restrict__ hout, int n, int relu) {
    int gid = blockIdx.x * blockDim.x + threadIdx.x;
    int w = gid >> 5, lane = gid & 31;
    if (w >= n) return;
    int beg = rowptr[w], end = rowptr[w + 1];
    float add = __ldg(&asum[w + n]);   // ad[w]

    // pass 1: score + store + online softmax stats
    float m = -3.4e38f, den = 0.f;
    for (int j = beg + lane; j < end; j += 32) {
        float v = __ldg(&asum[__ldg(&col[j])]) + add;
        v = v >= 0.f ? v : 0.2f * v;
        ev[j] = v;
        if (v > m) { den = den * __expf(m - v) + 1.f; m = v; }
        else den += __expf(v - m);
    }
#pragma unroll
    for (int o = 16; o > 0; o >>= 1) {
        float mo = __shfl_xor_sync(0xffffffffu, m, o);
        float dd = __shfl_xor_sync(0xffffffffu, den, o);
        float M = fmaxf(m, mo);
        den = den * __expf(m - M) + dd * __expf(mo - M);
        m = M;
    }
    float inv = 1.f / den;

    // pass 2: sequential ev read + hp gather
    float4 acc = make_float4(0.f, 0.f, 0.f, 0.f);
    int j = beg;
#pragma unroll 1
    for (; j + 4 <= end; j += 4) {
        int   s0 = __ldg(&col[j]),     s1 = __ldg(&col[j + 1]);
        int   s2 = __ldg(&col[j + 2]), s3 = __ldg(&col[j + 3]);
        float a0 = __expf(ev[j]     - m) * inv;
        float a1 = __expf(ev[j + 1] - m) * inv;
        float a2 = __expf(ev[j + 2] - m) * inv;
        float a3 = __expf(ev[j + 3] - m) * inv;
        float4 h0 = __ldg(&((const float4*)hp)[(long)s0 * 32 + lane]);
        float4 h1 = __ldg(&((const float4*)hp)[(long)s1 * 32 + lane]);
        float4 h2 = __ldg(&((const float4*)hp)[(long)s2 * 32 + lane]);
        float4 h3 = __ldg(&((const float4*)hp)[(long)s3 * 32 + lane]);
        acc.x = fmaf(a0, h0.x, acc.x); acc.y = fmaf(a0, h0.y, acc.y);
        acc.z = fmaf(a0, h0.z, acc.z); acc.w = fmaf(a0, h0.w, acc.w);
        acc.x = fmaf(a1, h1.x, acc.x); acc.y = fmaf(a1, h1.y, acc.y);
        acc.z = fmaf(a1, h1.z, acc.z); acc.w = fmaf(a1, h1.w, acc.w);
        acc.x = fmaf(a2, h2.x, acc.x); acc.y = fmaf(a2, h2.y, acc.y);
        acc.z = fmaf(a2, h2.z, acc.z); acc.w = fmaf(a2, h2.w, acc.w);
        acc.x = fmaf(a3, h3.x, acc.x); acc.y = fmaf(a3, h3.y, acc.y);
        acc.z = fmaf(a3, h3.z, acc.z); acc.w = fmaf(a3, h3.w, acc.w);
    }
    for (; j < end; j++) {
        int   s0 = __ldg(&col[j]);
        float a0 = __expf(ev[j] - m) * inv;
        float4 h0 = __ldg(&((const float4*)hp)[(long)s0 * 32 + lane]);
        acc.x = fmaf(a0, h0.x, acc.x); acc.y = fmaf(a0, h0.y, acc.y);
        acc.z = fmaf(a0, h0.z, acc.z); acc.w = fmaf(a0, h0.w, acc.w);
    }
    float4 bb = ((const float4*)bias)[lane];
    acc.x += bb.x; acc.y += bb.y; acc.z += bb.z; acc.w += bb.w;
    if (relu) {
        acc.x = fmaxf(acc.x, 0.f); acc.y = fmaxf(acc.y, 0.f);
        acc.z = fmaxf(acc.z, 0.f); acc.w = fmaxf(acc.w, 0.f);
    }
    ((float4*)hout)[(long)w * 32 + lane] = acc;
}

// global_add_pool over sorted batch
__global__ void k_pool(const float* __restrict__ h, const void* batch,
                       float* __restrict__ pool, int n) {
    __shared__ float s[GG * HH];
    for (int i = threadIdx.x; i < GG * HH; i += 256) s[i] = 0.f;
    __syncthreads();
    int is64 = g_is64;
    int per = (n + gridDim.x - 1) / gridDim.x;
    int i0 = blockIdx.x * per;
    int i1 = min(n, i0 + per);
    int c = threadIdx.x & 127, sub = threadIdx.x >> 7;
    float accv = 0.f; int curg = -1;
    for (int r = i0 + sub; r < i1; r += 2) {
        int g = ld_idx(batch, r, is64);
        if (g != curg) {
            if (curg >= 0) atomicAdd(&s[curg * HH + c], accv);
            accv = 0.f; curg = g;
        }
        accv += h[(long)r * HH + c];
    }
    if (curg >= 0) atomicAdd(&s[curg * HH + c], accv);
    __syncthreads();
    for (int i = threadIdx.x; i < GG * HH; i += 256) {
        float v = s[i];
        if (v != 0.f) atomicAdd(&pool[i], v);
    }
}

__global__ void k_final(const float* __restrict__ pool, const float* __restrict__ Wf,
                        const float* __restrict__ bf, float* __restrict__ out) {
    int i = blockIdx.x * blockDim.x + threadIdx.x;
    if (i >= GG * OO) return;
    int g = i >> 6, o = i & 63;
    float sa = bf[o];
#pragma unroll 8
    for (int k = 0; k < HH; k++) sa += pool[g * HH + k] * Wf[k * OO + o];
    out[i] = sa;
}

// ---------------- launch ----------------
extern "C" void kernel_launch(void* const* d_in, const int* in_sizes, int n_in,
                              void* d_out, int out_size) {
    const float* x     = (const float*)d_in[0];
    const void*  ei    = d_in[1];
    const void*  batch = d_in[2];
    const float* W0    = (const float*)d_in[3];
    const float* b0    = (const float*)d_in[4];
    const float* Wl    = (const float*)d_in[5];
    const float* a_src = (const float*)d_in[6];
    const float* a_dst = (const float*)d_in[7];
    const float* bl    = (const float*)d_in[8];
    const float* Wf    = (const float*)d_in[9];
    const float* bf    = (const float*)d_in[10];
    float* out = (float*)d_out;

    int n  = in_sizes[0] / HH;
    int E  = in_sizes[1] / 2;
    int et = E + n;
    int L  = in_sizes[5] / (HH * HH);

    float *h, *hp, *asp, *asum, *ev, *pool;
    int *counts, *part, *rowptr, *fillp, *bsum, *col;
    cudaGetSymbolAddress((void**)&h,    g_h);
    cudaGetSymbolAddress((void**)&hp,   g_hp);
    cudaGetSymbolAddress((void**)&asp,  g_asp);
    cudaGetSymbolAddress((void**)&asum, g_asum);
    cudaGetSymbolAddress((void**)&ev,   g_ev);
    cudaGetSymbolAddress((void**)&pool, g_pool);
    cudaGetSymbolAddress((void**)&counts, g_counts);
    cudaGetSymbolAddress((void**)&part,   g_part);
    cudaGetSymbolAddress((void**)&rowptr, g_rowptr);
    cudaGetSymbolAddress((void**)&fillp,  g_fillp);
    cudaGetSymbolAddress((void**)&bsum,   g_bsum);
    cudaGetSymbolAddress((void**)&col,    g_col);

    const int gemm_smem = (64 * 132 + 128 * 64) * sizeof(float);
    cudaFuncSetAttribute(k_gemm, cudaFuncAttributeMaxDynamicSharedMemorySize, gemm_smem);

    dim3 ggrid((n + 63) / 64, HH / 64);
    int nb = (n + 1023) / 1024;

    // slots 1-3 (so that slot 4 = k_gemm gets profiled by ncu -s 5 -c 1,
    // accounting for the 2 harness launches that precede ours)
    k_zero_i<<<(n + 255) / 256, 256>>>(counts, n);
    k_detect<<<1, 32>>>((const unsigned long long*)ei);
    k_hist<<<(et + 255) / 256, 256>>>(ei, counts, E, n);

    // slot 4: h = x @ W0 + b0
    k_gemm<<<ggrid, 128, gemm_smem>>>(x, W0, b0, nullptr, nullptr, nullptr, h, n);

    // CSR rest
    k_scanA<<<nb, 1024>>>(counts, part, bsum, n);
    k_scanC<<<(n + 255) / 256, 256>>>(part, bsum, counts, rowptr, fillp, n);
    k_fill<<<(et + 255) / 256, 256>>>(ei, fillp, col, E, n);

    for (int l = 0; l < L; l++) {
        k_gemm<<<ggrid, 128, gemm_smem>>>(h, Wl + (long)l * HH * HH, nullptr,
                                          a_src + l * HH, a_dst + l * HH,
                                          asp, hp, n);
        k_combine<<<(n + 255) / 256, 256>>>(asp, asum, n);
        k_aggregate<<<(n * 32 + 255) / 256, 256>>>(rowptr, col, asum, ev, hp,
                                                   bl + l * HH, h, n,
                                                   (l < L - 1) ? 1 : 0);
    }

    k_zero<<<(GG * HH / 4 + 255) / 256, 256>>>((float4*)pool, GG * HH / 4);
    k_pool<<<64, 256>>>(h, batch, pool, n);
    k_final<<<(GG * OO + 255) / 256, 256>>>(pool, Wf, bf, out);
}